// round 5
// baseline (speedup 1.0000x reference)
#include <cuda_runtime.h>
#include <cuda_bf16.h>
#include <cstdint>

// ---------------- problem constants ----------------
#define NMAX   200000
#define CCH    64
#define KTAPS  9
#define TN     128          // rows per block (MMA M)
#define NTHR   128
#define LEAK   0.01f
#define EPS_BN 1e-5f

// dynamic smem plane offsets (bytes): A hi/lo [128][64]bf16, B hi/lo [64][64]bf16
#define OFF_AHI 0
#define OFF_ALO 16384
#define OFF_BHI 32768
#define OFF_BLO 40960
#define DSM_BYTES 49152
#define SC_STRIDE 68        // epilogue fp32 tile stride (floats)

// ---------------- scratch (no cudaMalloc allowed) ----------------
__device__ float g_bufA[(size_t)NMAX * CCH];
__device__ float g_bufB[(size_t)NMAX * CCH];
// interleaved split planes: [row][hi 64 bf16 | lo 64 bf16], row N+... = zero pad row
__device__ __nv_bfloat16 g_fS[((size_t)NMAX + 1) * 128];
__device__ __nv_bfloat16 g_aS[((size_t)NMAX + 1) * 128];
__device__ __nv_bfloat16 g_wHi[4 * KTAPS * 64 * 64];  // [tensor][tap][o][c]
__device__ __nv_bfloat16 g_wLo[4 * KTAPS * 64 * 64];
__device__ float g_sums [4][CCH];
__device__ float g_sumsq[4][CCH];

// ---------------- helpers ----------------
__device__ __forceinline__ uint32_t smem_u32(const void* p) {
    uint32_t a;
    asm("{ .reg .u64 t; cvta.to.shared.u64 t, %1; cvt.u32.u64 %0, t; }" : "=r"(a) : "l"(p));
    return a;
}
__device__ __forceinline__ void ldsm4(uint32_t* r, uint32_t addr) {
    asm volatile("ldmatrix.sync.aligned.m8n8.x4.shared.b16 {%0,%1,%2,%3}, [%4];"
        : "=r"(r[0]), "=r"(r[1]), "=r"(r[2]), "=r"(r[3]) : "r"(addr));
}
__device__ __forceinline__ void mma16816(float* c, const uint32_t* a, const uint32_t* b) {
    asm volatile("mma.sync.aligned.m16n8k16.row.col.f32.bf16.bf16.f32 "
        "{%0,%1,%2,%3}, {%4,%5,%6,%7}, {%8,%9}, {%0,%1,%2,%3};"
        : "+f"(c[0]), "+f"(c[1]), "+f"(c[2]), "+f"(c[3])
        : "r"(a[0]), "r"(a[1]), "r"(a[2]), "r"(a[3]), "r"(b[0]), "r"(b[1]));
}

// ---------------- aux kernels ----------------
__global__ void zero_stats_k(int nTotal) {
    const int i = threadIdx.x;
    if (i < 512) { ((float*)g_sums)[i & 255] = 0.f; }   // covers sums+sumsq via two halves
    if (i < 256) ((float*)g_sums)[i]  = 0.f;
    else if (i < 512) ((float*)g_sumsq)[i - 256] = 0.f;
    // zero pad row (row nTotal) of both split buffers: 256 B each = 64 uints
    if (i < 64)  ((uint32_t*)(g_fS + (size_t)nTotal * 128))[i] = 0u;
    else if (i < 128) ((uint32_t*)(g_aS + (size_t)nTotal * 128))[i - 64] = 0u;
}

// weights [9][c][o] -> [tensor][tap][o][c] bf16 hi/lo planes
__global__ void prep_w_k(const float* __restrict__ w0, const float* __restrict__ w1,
                         const float* __restrict__ w2, const float* __restrict__ w3) {
    const int t = blockIdx.x / KTAPS, k = blockIdx.x % KTAPS;
    const float* w = (t == 0) ? w0 : (t == 1) ? w1 : (t == 2) ? w2 : w3;
    const float* src = w + k * 4096;
    __nv_bfloat16* dh = g_wHi + (size_t)(t * KTAPS + k) * 4096;
    __nv_bfloat16* dl = g_wLo + (size_t)(t * KTAPS + k) * 4096;
#pragma unroll
    for (int i = 0; i < 16; ++i) {
        const int j = threadIdx.x + i * 256;     // j = o*64 + c
        const int o = j >> 6, c = j & 63;
        const float v = src[c * 64 + o];
        __nv_bfloat16 bh = __float2bfloat16(v);
        dh[j] = bh;
        dl[j] = __float2bfloat16(v - __bfloat162float(bh));
    }
}

// fp32 rows -> interleaved bf16 hi/lo planes; AFFINE applies BN(stage) first
// (coefficients computed inline from g_sums/g_sumsq — no separate bn kernel)
template <bool AFFINE>
__global__ __launch_bounds__(256)
void split_k(const float* __restrict__ src, __nv_bfloat16* __restrict__ dst,
             int stage, const float* __restrict__ gamma,
             const float* __restrict__ beta, float invN, int nTotal)
{
    __shared__ float sc[64], sh[64];
    const int tid = threadIdx.x;
    if (AFFINE) {
        if (tid < 64) {
            const float m = g_sums[stage][tid] * invN;
            const float v = g_sumsq[stage][tid] * invN - m * m;
            const float a = gamma[tid] * rsqrtf(v + EPS_BN);
            sc[tid] = a;
            sh[tid] = beta[tid] - m * a;
        }
        __syncthreads();
    }
    const int row = blockIdx.x * 256 + tid;
    if (row >= nTotal) return;
    const float4* s = (const float4*)(src + (size_t)row * CCH);
    uint4* d = (uint4*)(dst + (size_t)row * 128);
    uint4 H[8], L[8];
#pragma unroll
    for (int g = 0; g < 8; ++g) {
        float4 v0 = s[2 * g], v1 = s[2 * g + 1];
        if (AFFINE) {
            const int c = g * 8;
            v0.x = fmaf(v0.x, sc[c + 0], sh[c + 0]);
            v0.y = fmaf(v0.y, sc[c + 1], sh[c + 1]);
            v0.z = fmaf(v0.z, sc[c + 2], sh[c + 2]);
            v0.w = fmaf(v0.w, sc[c + 3], sh[c + 3]);
            v1.x = fmaf(v1.x, sc[c + 4], sh[c + 4]);
            v1.y = fmaf(v1.y, sc[c + 5], sh[c + 5]);
            v1.z = fmaf(v1.z, sc[c + 6], sh[c + 6]);
            v1.w = fmaf(v1.w, sc[c + 7], sh[c + 7]);
        }
        float vv[8] = {v0.x, v0.y, v0.z, v0.w, v1.x, v1.y, v1.z, v1.w};
        uint16_t hh[8], ll[8];
#pragma unroll
        for (int e = 0; e < 8; ++e) {
            __nv_bfloat16 bh = __float2bfloat16(vv[e]);
            hh[e] = __bfloat16_as_ushort(bh);
            ll[e] = __bfloat16_as_ushort(__float2bfloat16(vv[e] - __bfloat162float(bh)));
        }
        H[g].x = (uint32_t)hh[0] | ((uint32_t)hh[1] << 16);
        H[g].y = (uint32_t)hh[2] | ((uint32_t)hh[3] << 16);
        H[g].z = (uint32_t)hh[4] | ((uint32_t)hh[5] << 16);
        H[g].w = (uint32_t)hh[6] | ((uint32_t)hh[7] << 16);
        L[g].x = (uint32_t)ll[0] | ((uint32_t)ll[1] << 16);
        L[g].y = (uint32_t)ll[2] | ((uint32_t)ll[3] << 16);
        L[g].z = (uint32_t)ll[4] | ((uint32_t)ll[5] << 16);
        L[g].w = (uint32_t)ll[6] | ((uint32_t)ll[7] << 16);
    }
#pragma unroll
    for (int g = 0; g < 8; ++g) d[g] = H[g];
#pragma unroll
    for (int g = 0; g < 8; ++g) d[8 + g] = L[g];
}

// ---------------- main conv kernel (mma.sync bf16, 3-term) ----------------
__global__ __launch_bounds__(NTHR)
void conv_mma_k(const __nv_bfloat16* __restrict__ src,   // [N+1][128] hi|lo
                const int* __restrict__ nbr,
                int wtIdx, float* __restrict__ dst, int nTotal, int stage)
{
    extern __shared__ char smemc[];

    const int tid   = threadIdx.x;
    const int lane  = tid & 31;
    const int wid   = tid >> 5;
    const int nBase = blockIdx.x * TN;
    const bool rowOK = (nBase + tid) < nTotal;

    const uint32_t sbase = smem_u32(smemc);
    const int rowBase = wid * 32;
    const int lsw = lane & 7, l15 = lane & 15, l16 = lane >> 4;

    // preload all 9 neighbor ids (coalesced 36B/thread)
    int nb[KTAPS];
#pragma unroll
    for (int k = 0; k < KTAPS; ++k)
        nb[k] = rowOK ? nbr[(size_t)(nBase + tid) * KTAPS + k] : nTotal;

    float C[2][8][4];
#pragma unroll
    for (int mt = 0; mt < 2; ++mt)
#pragma unroll
        for (int nt = 0; nt < 8; ++nt)
#pragma unroll
            for (int i = 0; i < 4; ++i) C[mt][nt][i] = 0.f;

    const __nv_bfloat16* wHiT = g_wHi + (size_t)(wtIdx * KTAPS) * 4096;
    const __nv_bfloat16* wLoT = g_wLo + (size_t)(wtIdx * KTAPS) * 4096;

    char* aHiRow = smemc + OFF_AHI + tid * 128;
    char* aLoRow = smemc + OFF_ALO + tid * 128;
    const int rsw = tid & 7;

    for (int k = 0; k < KTAPS; ++k) {
        __syncthreads();   // prior tap's ldmatrix reads done

        // ---- gather A row (thread = row): pure copy, pad row is zero ----
        {
            const uint4* arow = (const uint4*)(src + (size_t)nb[k] * 128);
#pragma unroll
            for (int g = 0; g < 8; ++g) {
                const int off = (g ^ rsw) << 4;
                *(uint4*)(aHiRow + off) = arow[g];
                *(uint4*)(aLoRow + off) = arow[8 + g];
            }
        }
        // ---- B planes [n=o][k=c] bf16, swizzled ----
        {
            const __nv_bfloat16* bh = wHiT + (size_t)k * 4096;
            const __nv_bfloat16* bl = wLoT + (size_t)k * 4096;
#pragma unroll
            for (int i = 0; i < 4; ++i) {
                const int id = tid * 4 + i;          // 0..511 16B chunks
                const int n = id >> 3, kg = id & 7;
                const int srcOff = n * 64 + kg * 8;
                const int dstOff = n * 128 + ((kg ^ (n & 7)) << 4);
                *(uint4*)(smemc + OFF_BHI + dstOff) = *(const uint4*)(bh + srcOff);
                *(uint4*)(smemc + OFF_BLO + dstOff) = *(const uint4*)(bl + srcOff);
            }
        }
        __syncthreads();

        // ---- 4 k16 chunks: ldmatrix + 48 MMAs each ----
#pragma unroll
        for (int q = 0; q < 4; ++q) {
            const int kg = 2 * q + l16;
            uint32_t ah[2][4], al[2][4];
#pragma unroll
            for (int mt = 0; mt < 2; ++mt) {
                const uint32_t off =
                    (uint32_t)((rowBase + mt * 16 + l15) * 128 + ((kg ^ lsw) << 4));
                ldsm4(ah[mt], sbase + OFF_AHI + off);
                ldsm4(al[mt], sbase + OFF_ALO + off);
            }
            uint32_t bh[8][2], bl[8][2];
#pragma unroll
            for (int p = 0; p < 4; ++p) {
                const uint32_t off =
                    (uint32_t)((16 * p + l15) * 128 + ((kg ^ lsw) << 4));
                uint32_t r[4];
                ldsm4(r, sbase + OFF_BHI + off);
                bh[2*p][0] = r[0]; bh[2*p+1][0] = r[1];
                bh[2*p][1] = r[2]; bh[2*p+1][1] = r[3];
                ldsm4(r, sbase + OFF_BLO + off);
                bl[2*p][0] = r[0]; bl[2*p+1][0] = r[1];
                bl[2*p][1] = r[2]; bl[2*p+1][1] = r[3];
            }
#pragma unroll
            for (int mt = 0; mt < 2; ++mt)
#pragma unroll
                for (int nt = 0; nt < 8; ++nt) {
                    mma16816(C[mt][nt], ah[mt], bh[nt]);
                    mma16816(C[mt][nt], ah[mt], bl[nt]);
                    mma16816(C[mt][nt], al[mt], bh[nt]);
                }
        }
    }

    // ---- epilogue: leaky on frags -> smem fp32 tile -> store + stats ----
    __syncthreads();
    float* sC = (float*)smemc;                   // [128][SC_STRIDE]
    const int fg = lane >> 2, ft2 = (lane & 3) * 2;
#pragma unroll
    for (int mt = 0; mt < 2; ++mt)
#pragma unroll
        for (int nt = 0; nt < 8; ++nt) {
            float* c = C[mt][nt];
#pragma unroll
            for (int i = 0; i < 4; ++i)
                c[i] = (c[i] > 0.f) ? c[i] : LEAK * c[i];
            const int r0 = rowBase + mt * 16 + fg;
            const int col = nt * 8 + ft2;
            *(float2*)&sC[r0 * SC_STRIDE + col]       = make_float2(c[0], c[1]);
            *(float2*)&sC[(r0 + 8) * SC_STRIDE + col] = make_float2(c[2], c[3]);
        }
    __syncthreads();

    if (rowOK) {
        float4* drow = (float4*)(dst + (size_t)(nBase + tid) * CCH);
        const float4* rowp = (const float4*)(sC + tid * SC_STRIDE);
#pragma unroll
        for (int c4 = 0; c4 < 16; ++c4) drow[c4] = rowp[c4];
    }

    {
        const int ch = tid >> 1, half = tid & 1;
        float s = 0.f, s2 = 0.f;
#pragma unroll 8
        for (int i = 0; i < 64; ++i) {
            const float v = sC[(half * 64 + i) * SC_STRIDE + ch];
            s += v; s2 += v * v;
        }
        s  += __shfl_xor_sync(0xffffffffu, s, 1);
        s2 += __shfl_xor_sync(0xffffffffu, s2, 1);
        if (!half) {
            atomicAdd(&g_sums[stage][ch], s);
            atomicAdd(&g_sumsq[stage][ch], s2);
        }
    }
}

// out = BN3(out) + BN1(y2); coefficients for stages 1,3 computed inline
__global__ __launch_bounds__(256)
void final_k(float* __restrict__ out, const float* __restrict__ y2,
             const float* __restrict__ g1_, const float* __restrict__ b1_,
             const float* __restrict__ g3_, const float* __restrict__ b3_,
             float invN, int total4)
{
    __shared__ float c1[64], s1[64], c3[64], s3[64];
    const int tid = threadIdx.x;
    if (tid < 64) {
        const float m1 = g_sums[1][tid] * invN;
        const float v1 = g_sumsq[1][tid] * invN - m1 * m1;
        const float a1 = g1_[tid] * rsqrtf(v1 + EPS_BN);
        c1[tid] = a1; s1[tid] = b1_[tid] - m1 * a1;
        const float m3 = g_sums[3][tid] * invN;
        const float v3 = g_sumsq[3][tid] * invN - m3 * m3;
        const float a3 = g3_[tid] * rsqrtf(v3 + EPS_BN);
        c3[tid] = a3; s3[tid] = b3_[tid] - m3 * a3;
    }
    __syncthreads();
    const int i = blockIdx.x * 256 + tid;
    if (i >= total4) return;
    float4 a = ((float4*)out)[i];
    const float4 b = ((const float4*)y2)[i];
    const int c = (i * 4) & 63;
    a.x = fmaf(a.x, c3[c + 0], s3[c + 0]) + fmaf(b.x, c1[c + 0], s1[c + 0]);
    a.y = fmaf(a.y, c3[c + 1], s3[c + 1]) + fmaf(b.y, c1[c + 1], s1[c + 1]);
    a.z = fmaf(a.z, c3[c + 2], s3[c + 2]) + fmaf(b.z, c1[c + 2], s1[c + 2]);
    a.w = fmaf(a.w, c3[c + 3], s3[c + 3]) + fmaf(b.w, c1[c + 3], s1[c + 3]);
    ((float4*)out)[i] = a;
}

// ---------------- launcher ----------------
extern "C" void kernel_launch(void* const* d_in, const int* in_sizes, int n_in,
                              void* d_out, int out_size)
{
    const float* features = (const float*)d_in[0];
    const float* w1   = (const float*)d_in[1];
    const float* w1_2 = (const float*)d_in[2];
    const float* w2   = (const float*)d_in[3];
    const float* w3   = (const float*)d_in[4];
    const float* g0   = (const float*)d_in[5];
    const float* b0   = (const float*)d_in[6];
    const float* g0_2 = (const float*)d_in[7];
    const float* b0_2 = (const float*)d_in[8];
    const float* g1   = (const float*)d_in[9];
    const float* b1   = (const float*)d_in[10];
    const float* g2   = (const float*)d_in[11];
    const float* b2   = (const float*)d_in[12];
    const int*   nbr13 = (const int*)d_in[13];
    const int*   nbr31 = (const int*)d_in[14];

    const int nTotal = in_sizes[0] / CCH;
    const float invN = 1.0f / (float)nTotal;
    const int grid   = (nTotal + TN - 1) / TN;
    const int gridS  = (nTotal + 255) / 256;

    cudaFuncSetAttribute(conv_mma_k, cudaFuncAttributeMaxDynamicSharedMemorySize, DSM_BYTES);

    float *bufA = nullptr, *bufB = nullptr;
    __nv_bfloat16 *fS = nullptr, *aS = nullptr;
    cudaGetSymbolAddress((void**)&bufA, g_bufA);
    cudaGetSymbolAddress((void**)&bufB, g_bufB);
    cudaGetSymbolAddress((void**)&fS, g_fS);
    cudaGetSymbolAddress((void**)&aS, g_aS);
    float* out = (float*)d_out;

    zero_stats_k<<<1, 512>>>(nTotal);
    prep_w_k<<<4 * KTAPS, 256>>>(w1, w1_2, w2, w3);
    split_k<false><<<gridS, 256>>>(features, fS, 0, nullptr, nullptr, invN, nTotal);

    // shortcut branch: conv(nbr13,w1) -> BN0 -> conv(nbr31,w1_2) [stats 0,1]
    conv_mma_k<<<grid, NTHR, DSM_BYTES>>>(fS, nbr13, 0, bufA, nTotal, 0);
    split_k<true ><<<gridS, 256>>>(bufA, aS, 0, g0, b0, invN, nTotal);
    conv_mma_k<<<grid, NTHR, DSM_BYTES>>>(aS, nbr31, 1, bufB, nTotal, 1);

    // main branch: conv(nbr31,w2) -> BN2 -> conv(nbr13,w3) [stats 2,3]
    conv_mma_k<<<grid, NTHR, DSM_BYTES>>>(fS, nbr31, 2, bufA, nTotal, 2);
    split_k<true ><<<gridS, 256>>>(bufA, aS, 2, g1, b1, invN, nTotal);
    conv_mma_k<<<grid, NTHR, DSM_BYTES>>>(aS, nbr13, 3, out, nTotal, 3);

    // out = BN3(out) + BN1(bufB)
    const int total4 = nTotal * CCH / 4;
    final_k<<<(total4 + 255) / 256, 256>>>(out, bufB, g0_2, b0_2, g2, b2,
                                           invN, total4);
}